// round 13
// baseline (speedup 1.0000x reference)
#include <cuda_runtime.h>
#include <math.h>

#define NB 128
#define NA 96
#define NATOMS (NB*NA)      // 12288
#define NIN 128
#define H1 64

typedef unsigned long long ull;

// ---------------- scratch (static device memory, no allocations) ----------------
__device__ float g_vmix[NATOMS*3*NIN];        // 36864 x 128
__device__ float g_h1[NATOMS*NIN];            // 12288 x 128
__device__ float g_x2[NATOMS*NIN];            // 12288 x 128
__device__ float g_l0[NATOMS];
__device__ float g_l1[NATOMS*3];

__device__ __forceinline__ float silu_f(float x) {
    return __fdividef(x, 1.0f + __expf(-x));
}
// fast silu via HW tanh: x*sigmoid(x) = y + y*tanh(y), y = x/2
__device__ __forceinline__ float silu_t(float x) {
    float y = 0.5f*x, t;
    asm("tanh.approx.f32 %0, %1;" : "=f"(t) : "f"(y));
    return fmaf(y, t, y);
}
__device__ __forceinline__ ull packf2(float lo, float hi) {
    ull r; asm("mov.b64 %0, {%1, %2};" : "=l"(r) : "f"(lo), "f"(hi)); return r;
}
__device__ __forceinline__ ull dupf2(float v) {
    ull r; asm("mov.b64 %0, {%1, %1};" : "=l"(r) : "f"(v)); return r;
}
__device__ __forceinline__ void unpackf2(ull v, float& lo, float& hi) {
    asm("mov.b64 {%0, %1}, %2;" : "=f"(lo), "=f"(hi) : "l"(v));
}
__device__ __forceinline__ ull ffma2(ull a, ull b, ull c) {
    ull d; asm("fma.rn.f32x2 %0, %1, %2, %3;" : "=l"(d) : "l"(a), "l"(b), "l"(c)); return d;
}

// ---------------- 32x128 SGEMM, double-buffered, f32x2 mainloop -------------------
// C = A(MxK)@B(Kx128)(+bias)(+silu)
// X1 mode: A column k<128 comes from srep (stride 128); k>=128 is ||vmix[n,:, k-128]||
template<int K, bool BIAS, bool SILU, bool X1>
__global__ __launch_bounds__(256) void sgemm32(
    const float* __restrict__ A, const float* __restrict__ B,
    const float* __restrict__ bias, float* __restrict__ C)
{
    __shared__ __align__(16) float As[2][16][36];
    __shared__ __align__(16) float Bs[2][16][128];
    const int tid = threadIdx.x;
    const int bm  = blockIdx.x * 32;
    const int ty  = tid >> 5;    // 0..7  -> rows ty*4..+3
    const int tx  = tid & 31;    // 0..31 -> cols tx*4..+3

    // A-load indices: 2 elems/thread
    const int am0 = (tid)       >> 4, ak0 = (tid)       & 15;
    const int am1 = (tid + 256) >> 4, ak1 = (tid + 256) & 15;

    float ra[2];
    float rb[8];

    auto loadA = [&](int k0, float* r) {
#pragma unroll
        for (int i = 0; i < 2; i++) {
            int m  = (i == 0) ? am0 : am1;
            int kk = (i == 0) ? ak0 : ak1;
            int k  = k0 + kk;
            int n  = bm + m;
            float v;
            if (X1) {
                if (k < 128) {
                    v = A[n*128 + k];
                } else {
                    int o = k - 128;
                    float a = g_vmix[(n*3+0)*128 + o];
                    float b = g_vmix[(n*3+1)*128 + o];
                    float d = g_vmix[(n*3+2)*128 + o];
                    v = sqrtf(a*a + b*b + d*d);
                }
            } else {
                v = A[n*K + k];
            }
            r[i] = v;
        }
    };
    auto loadB = [&](int k0, float* r) {
#pragma unroll
        for (int i = 0; i < 8; i++) {
            int idx = tid + i*256;
            int kk = idx >> 7, n = idx & 127;
            r[i] = B[(k0 + kk)*128 + n];
        }
    };
    auto stsA = [&](int buf, const float* r) {
        As[buf][ak0][am0] = r[0];
        As[buf][ak1][am1] = r[1];
    };
    auto stsB = [&](int buf, const float* r) {
#pragma unroll
        for (int i = 0; i < 8; i++) {
            int idx = tid + i*256;
            int kk = idx >> 7, n = idx & 127;
            Bs[buf][kk][n] = r[i];
        }
    };

    // packed accumulators: accp[i][0] = cols (4tx, 4tx+1), accp[i][1] = cols (4tx+2, 4tx+3)
    ull accp[4][2];
#pragma unroll
    for (int i = 0; i < 4; i++) { accp[i][0] = 0ull; accp[i][1] = 0ull; }

    loadA(0, ra); loadB(0, rb);
    stsA(0, ra);  stsB(0, rb);
    __syncthreads();

    const int NCH = K / 16;
#pragma unroll 2
    for (int ch = 0; ch < NCH; ch++) {
        int cur = ch & 1;
        if (ch + 1 < NCH) { loadA((ch+1)*16, ra); loadB((ch+1)*16, rb); }
#pragma unroll
        for (int kk = 0; kk < 16; kk++) {
            float4 a = *reinterpret_cast<const float4*>(&As[cur][kk][ty*4]);
            const ull* bp = reinterpret_cast<const ull*>(&Bs[cur][kk][tx*4]);
            ull b01 = bp[0], b23 = bp[1];
            ull a0 = dupf2(a.x), a1 = dupf2(a.y), a2 = dupf2(a.z), a3 = dupf2(a.w);
            accp[0][0] = ffma2(a0, b01, accp[0][0]); accp[0][1] = ffma2(a0, b23, accp[0][1]);
            accp[1][0] = ffma2(a1, b01, accp[1][0]); accp[1][1] = ffma2(a1, b23, accp[1][1]);
            accp[2][0] = ffma2(a2, b01, accp[2][0]); accp[2][1] = ffma2(a2, b23, accp[2][1]);
            accp[3][0] = ffma2(a3, b01, accp[3][0]); accp[3][1] = ffma2(a3, b23, accp[3][1]);
        }
        if (ch + 1 < NCH) {
            stsA(1-cur, ra); stsB(1-cur, rb);
            __syncthreads();
        }
    }

#pragma unroll
    for (int i = 0; i < 4; i++) {
        int row = bm + ty*4 + i;
        float f[4];
        unpackf2(accp[i][0], f[0], f[1]);
        unpackf2(accp[i][1], f[2], f[3]);
        float4 v;
#pragma unroll
        for (int j = 0; j < 4; j++) {
            int col = tx*4 + j;
            float x = f[j];
            if (BIAS) x += bias[col];
            if (SILU) x = silu_f(x);
            f[j] = x;
        }
        v.x=f[0]; v.y=f[1]; v.z=f[2]; v.w=f[3];
        *reinterpret_cast<float4*>(&C[row*128 + tx*4]) = v;
    }
}

// ---------------- gated block 2: one atom per warp, f32x2 GEMV ---------------------
// Lane owns output columns (2*lane, 2*lane+1): W1 rows via LDS.64 as packed f32x2.
__global__ __launch_bounds__(256) void block2_kernel(
    const float* __restrict__ mixW2, const float* __restrict__ W1,
    const float* __restrict__ b1,    const float* __restrict__ W2,
    const float* __restrict__ b2)
{
    __shared__ __align__(16) float sW1[65*64];
    __shared__ __align__(16) float sb1v[64], sW2v[128], sMix[128], sb2v[2];
    __shared__ float sx_buf[8][64];
    const int tid = threadIdx.x;
    for (int t = tid; t < 65*64/4; t += 256)
        reinterpret_cast<float4*>(sW1)[t] = reinterpret_cast<const float4*>(W1)[t];
    if (tid < 64)  sb1v[tid] = b1[tid];
    if (tid < 128) { sW2v[tid] = W2[tid]; sMix[tid] = mixW2[tid]; }
    if (tid < 2)   sb2v[tid] = b2[tid];
    __syncthreads();

    const int warp = tid >> 5, lane = tid & 31;
    const int n = blockIdx.x*8 + warp;

    const float m0a = sMix[lane*2],        m1a = sMix[lane*2+1];
    const float m0b = sMix[(lane+32)*2],   m1b = sMix[(lane+32)*2+1];

    float x2a = g_x2[n*128 + lane],      x2b = g_x2[n*128 + 32 + lane];
    float ga  = g_x2[n*128 + 64 + lane], gb  = g_x2[n*128 + 96 + lane];
    float pm[6];
#pragma unroll
    for (int d = 0; d < 3; d++) {
        float vWa = g_vmix[(n*3+d)*128 + 64 + lane];
        float vWb = g_vmix[(n*3+d)*128 + 96 + lane];
        float v1a = ga*vWa, v1b = gb*vWb;
        pm[d*2]   = v1a*m0a + v1b*m0b;
        pm[d*2+1] = v1a*m1a + v1b*m1b;
    }
#pragma unroll
    for (int off = 16; off > 0; off >>= 1)
#pragma unroll
        for (int q = 0; q < 6; q++)
            pm[q] += __shfl_xor_sync(0xffffffffu, pm[q], off);

    float vn = sqrtf(pm[0]*pm[0] + pm[2]*pm[2] + pm[4]*pm[4]);
    sx_buf[warp][lane] = silu_f(x2a); sx_buf[warp][lane+32] = silu_f(x2b);
    __syncwarp();

    const ull* W1d = reinterpret_cast<const ull*>(sW1);
    float2 b1p = reinterpret_cast<const float2*>(sb1v)[lane];
    float2 wvn = reinterpret_cast<const float2*>(sW1)[64*32 + lane];
    ull h2 = packf2(fmaf(vn, wvn.x, b1p.x), fmaf(vn, wvn.y, b1p.y));
#pragma unroll 16
    for (int k = 0; k < 64; k++) {
        ull svp = dupf2(sx_buf[warp][k]);
        h2 = ffma2(svp, W1d[k*32 + lane], h2);
    }
    float h2x, h2y; unpackf2(h2, h2x, h2y);
    h2x = silu_f(h2x); h2y = silu_f(h2y);
    float4 w2 = reinterpret_cast<const float4*>(sW2v)[lane];   // W2[2lane][0..1], W2[2lane+1][0..1]
    float y0 = h2x*w2.x + h2y*w2.z;
    float y1 = h2x*w2.y + h2y*w2.w;
#pragma unroll
    for (int off = 16; off > 0; off >>= 1) {
        y0 += __shfl_xor_sync(0xffffffffu, y0, off);
        y1 += __shfl_xor_sync(0xffffffffu, y1, off);
    }
    if (lane == 0) {
        g_l0[n] = y0 + sb2v[0];
        float g2 = y1 + sb2v[1];
        g_l1[n*3+0] = g2*pm[1];
        g_l1[n*3+1] = g2*pm[3];
        g_l1[n*3+2] = g2*pm[5];
    }
}

// ---------------- pairwise kernel: warp per i, 3 j's per lane, f32x2 packed --------
__global__ __launch_bounds__(256) void pair_kernel(
    const float* __restrict__ positions,
    const float* __restrict__ vvW1, const float* __restrict__ vvb1,
    const float* __restrict__ vvW2, const float* __restrict__ vvb2,
    const float* __restrict__ vrW1, const float* __restrict__ vrb1,
    const float* __restrict__ vrW2, const float* __restrict__ vrb2,
    const float* __restrict__ sW1,  const float* __restrict__ sb1,
    const float* __restrict__ sW2,  const float* __restrict__ sb2,
    const float* __restrict__ hW1,  const float* __restrict__ hb1,
    const float* __restrict__ hW2,  const float* __restrict__ hb2,
    float* __restrict__ out)
{
    __shared__ float s_vvW1[270], s_vrW1[270];
    __shared__ float s_vvb1[30], s_vrb1[30], s_sb1[30], s_hb1[30];
    __shared__ float s_sW1a[30], s_sW1b[30];
    __shared__ ull   s_vvW2p[30][4]; __shared__ float s_vvW2s[30];
    __shared__ ull   s_vrW2p[30][4]; __shared__ float s_vrW2s[30];
    __shared__ ull   s_sW2p[30][4];  __shared__ float s_sW2s[30];
    __shared__ ull   s_hW2p[30][4];  __shared__ float s_hW2s[30];
    __shared__ ull   s_hW1p[30][4];  __shared__ float s_hW1s[30];
    __shared__ float s_acc0[9], s_hb2[9];
    __shared__ float s_l1[NA*3], s_pos[NA*3], s_l0[NA];
    __shared__ float4 s_Ai4[8][30], s_Ari4[8][30];
    __shared__ float  s_Ci[8][30];

    const int tid  = threadIdx.x;
    const int b    = blockIdx.y;
    const int warp = tid >> 5, lane = tid & 31;
    const int i    = blockIdx.x*8 + warp;

    for (int t = tid; t < 270; t += 256) { s_vvW1[t] = vvW1[t]; s_vrW1[t] = vrW1[t]; }
    for (int t = tid; t < 120; t += 256) {
        int c = t >> 2, q = t & 3;
        s_vvW2p[c][q] = packf2(vvW2[c*9+2*q], vvW2[c*9+2*q+1]);
        s_vrW2p[c][q] = packf2(vrW2[c*9+2*q], vrW2[c*9+2*q+1]);
        s_sW2p[c][q]  = packf2(sW2 [c*9+2*q], sW2 [c*9+2*q+1]);
        s_hW2p[c][q]  = packf2(hW2 [c*9+2*q], hW2 [c*9+2*q+1]);
        s_hW1p[c][q]  = packf2(hW1[(2*q)*30+c], hW1[(2*q+1)*30+c]);
    }
    if (tid < 30) {
        s_vvW2s[tid] = vvW2[tid*9+8]; s_vrW2s[tid] = vrW2[tid*9+8];
        s_sW2s[tid]  = sW2[tid*9+8];  s_hW2s[tid]  = hW2[tid*9+8];
        s_hW1s[tid]  = hW1[8*30+tid];
        s_vvb1[tid]  = vvb1[tid]; s_vrb1[tid] = vrb1[tid];
        s_sb1[tid]   = sb1[tid];  s_hb1[tid]  = hb1[tid];
        s_sW1a[tid]  = sW1[tid];  s_sW1b[tid] = sW1[30+tid];
    }
    if (tid < 9) { s_hb2[tid] = hb2[tid]; s_acc0[tid] = vvb2[tid]+vrb2[tid]+sb2[tid]; }

    const int nbase = b*NA;
    for (int t = tid; t < NA*3; t += 256) { s_l1[t] = g_l1[nbase*3 + t]; s_pos[t] = positions[nbase*3 + t]; }
    for (int t = tid; t < NA;   t += 256) s_l0[t] = g_l0[nbase + t];
    __syncthreads();

    // per-warp precompute for fixed i: A[c][l] = sum_k l1i[k]*W1[(3k+l)*30+c], [3]=bias
    const float l1i0 = s_l1[i*3], l1i1 = s_l1[i*3+1], l1i2 = s_l1[i*3+2];
    const float l0i  = s_l0[i];
    for (int c = lane; c < 30; c += 32) {
        float a[3], ar[3];
#pragma unroll
        for (int l = 0; l < 3; l++) {
            a[l]  = l1i0*s_vvW1[l*30+c] + l1i1*s_vvW1[(3+l)*30+c] + l1i2*s_vvW1[(6+l)*30+c];
            ar[l] = l1i0*s_vrW1[l*30+c] + l1i1*s_vrW1[(3+l)*30+c] + l1i2*s_vrW1[(6+l)*30+c];
        }
        s_Ai4[warp][c]  = make_float4(a[0],  a[1],  a[2],  s_vvb1[c]);
        s_Ari4[warp][c] = make_float4(ar[0], ar[1], ar[2], s_vrb1[c]);
        s_Ci[warp][c]   = s_sb1[c] + l0i*s_sW1a[c];
    }
    __syncwarp();

    float vj[3][3], pj[3][3], l0j[3];
#pragma unroll
    for (int r = 0; r < 3; r++) {
        int j = lane + r*32;
#pragma unroll
        for (int l = 0; l < 3; l++) { vj[r][l] = s_l1[j*3+l]; pj[r][l] = s_pos[j*3+l]; }
        l0j[r] = s_l0[j];
    }

    ull   accp[3][4];
    float acc8[3];
#pragma unroll
    for (int r = 0; r < 3; r++) {
#pragma unroll
        for (int q = 0; q < 4; q++) accp[r][q] = packf2(s_acc0[2*q], s_acc0[2*q+1]);
        acc8[r] = s_acc0[8];
    }

    // vv MLP
#pragma unroll 2
    for (int c = 0; c < 30; c++) {
        float4 A = s_Ai4[warp][c];
        ull w0 = s_vvW2p[c][0], w1 = s_vvW2p[c][1], w2 = s_vvW2p[c][2], w3 = s_vvW2p[c][3];
        float w8 = s_vvW2s[c];
#pragma unroll
        for (int r = 0; r < 3; r++) {
            float x = fmaf(A.x, vj[r][0], fmaf(A.y, vj[r][1], fmaf(A.z, vj[r][2], A.w)));
            float h = silu_t(x);
            ull hp = packf2(h, h);
            accp[r][0] = ffma2(hp, w0, accp[r][0]);
            accp[r][1] = ffma2(hp, w1, accp[r][1]);
            accp[r][2] = ffma2(hp, w2, accp[r][2]);
            accp[r][3] = ffma2(hp, w3, accp[r][3]);
            acc8[r] = fmaf(h, w8, acc8[r]);
        }
    }
    // vr MLP
#pragma unroll 2
    for (int c = 0; c < 30; c++) {
        float4 A = s_Ari4[warp][c];
        ull w0 = s_vrW2p[c][0], w1 = s_vrW2p[c][1], w2 = s_vrW2p[c][2], w3 = s_vrW2p[c][3];
        float w8 = s_vrW2s[c];
#pragma unroll
        for (int r = 0; r < 3; r++) {
            float x = fmaf(A.x, pj[r][0], fmaf(A.y, pj[r][1], fmaf(A.z, pj[r][2], A.w)));
            float h = silu_t(x);
            ull hp = packf2(h, h);
            accp[r][0] = ffma2(hp, w0, accp[r][0]);
            accp[r][1] = ffma2(hp, w1, accp[r][1]);
            accp[r][2] = ffma2(hp, w2, accp[r][2]);
            accp[r][3] = ffma2(hp, w3, accp[r][3]);
            acc8[r] = fmaf(h, w8, acc8[r]);
        }
    }
    // sp MLP
#pragma unroll 2
    for (int c = 0; c < 30; c++) {
        float ci = s_Ci[warp][c], wb = s_sW1b[c];
        ull w0 = s_sW2p[c][0], w1 = s_sW2p[c][1], w2 = s_sW2p[c][2], w3 = s_sW2p[c][3];
        float w8 = s_sW2s[c];
#pragma unroll
        for (int r = 0; r < 3; r++) {
            float h = silu_t(fmaf(l0j[r], wb, ci));
            ull hp = packf2(h, h);
            accp[r][0] = ffma2(hp, w0, accp[r][0]);
            accp[r][1] = ffma2(hp, w1, accp[r][1]);
            accp[r][2] = ffma2(hp, w2, accp[r][2]);
            accp[r][3] = ffma2(hp, w3, accp[r][3]);
            acc8[r] = fmaf(h, w8, acc8[r]);
        }
    }
    // final h MLP
    ull   o9p[3][4];
    float o9s[3];
#pragma unroll
    for (int r = 0; r < 3; r++) {
#pragma unroll
        for (int q = 0; q < 4; q++) o9p[r][q] = packf2(s_hb2[2*q], s_hb2[2*q+1]);
        o9s[r] = s_hb2[8];
    }
#pragma unroll 2
    for (int c = 0; c < 30; c++) {
        ull a0 = s_hW1p[c][0], a1 = s_hW1p[c][1], a2 = s_hW1p[c][2], a3 = s_hW1p[c][3];
        float a8 = s_hW1s[c], bb = s_hb1[c];
        ull b0 = s_hW2p[c][0], b1 = s_hW2p[c][1], b2 = s_hW2p[c][2], b3 = s_hW2p[c][3];
        float b8 = s_hW2s[c];
#pragma unroll
        for (int r = 0; r < 3; r++) {
            ull hs = packf2(bb, 0.f);
            hs = ffma2(accp[r][0], a0, hs);
            hs = ffma2(accp[r][1], a1, hs);
            hs = ffma2(accp[r][2], a2, hs);
            hs = ffma2(accp[r][3], a3, hs);
            float lo, hi; unpackf2(hs, lo, hi);
            float x = fmaf(acc8[r], a8, lo + hi);
            float h = silu_t(x);
            ull hp = packf2(h, h);
            o9p[r][0] = ffma2(hp, b0, o9p[r][0]);
            o9p[r][1] = ffma2(hp, b1, o9p[r][1]);
            o9p[r][2] = ffma2(hp, b2, o9p[r][2]);
            o9p[r][3] = ffma2(hp, b3, o9p[r][3]);
            o9s[r] = fmaf(h, b8, o9s[r]);
        }
    }
    // write: out[((b*A+i)*3+k)*(3A) + j*3 + l], t = 3k+l
    const int rowbase = (b*NA + i)*3;
#pragma unroll
    for (int r = 0; r < 3; r++) {
        float f[9];
#pragma unroll
        for (int q = 0; q < 4; q++) unpackf2(o9p[r][q], f[2*q], f[2*q+1]);
        f[8] = o9s[r];
        int j = lane + r*32;
#pragma unroll
        for (int k = 0; k < 3; k++)
#pragma unroll
            for (int l = 0; l < 3; l++)
                out[(rowbase + k)*(3*NA) + j*3 + l] = f[3*k + l];
    }
}

// ---------------- launcher ----------------------------------------------------------
extern "C" void kernel_launch(void* const* d_in, const int* in_sizes, int n_in,
                              void* d_out, int out_size)
{
    (void)in_sizes; (void)n_in; (void)out_size;
    const float* positions  = (const float*)d_in[0];
    const float* scalar_rep = (const float*)d_in[1];
    const float* vector_rep = (const float*)d_in[2];
    const float* mix_W1 = (const float*)d_in[3];
    const float* sc1_W1 = (const float*)d_in[4];
    const float* sc1_b1 = (const float*)d_in[5];
    const float* sc1_W2 = (const float*)d_in[6];
    const float* sc1_b2 = (const float*)d_in[7];
    const float* mix_W2 = (const float*)d_in[8];
    const float* sc2_W1 = (const float*)d_in[9];
    const float* sc2_b1 = (const float*)d_in[10];
    const float* sc2_W2 = (const float*)d_in[11];
    const float* sc2_b2 = (const float*)d_in[12];
    const float* vv_W1  = (const float*)d_in[13];
    const float* vv_b1  = (const float*)d_in[14];
    const float* vv_W2  = (const float*)d_in[15];
    const float* vv_b2  = (const float*)d_in[16];
    const float* vr_W1  = (const float*)d_in[17];
    const float* vr_b1  = (const float*)d_in[18];
    const float* vr_W2  = (const float*)d_in[19];
    const float* vr_b2  = (const float*)d_in[20];
    const float* s_W1   = (const float*)d_in[21];
    const float* s_b1   = (const float*)d_in[22];
    const float* s_W2   = (const float*)d_in[23];
    const float* s_b2   = (const float*)d_in[24];
    const float* h_W1   = (const float*)d_in[25];
    const float* h_b1   = (const float*)d_in[26];
    const float* h_W2   = (const float*)d_in[27];
    const float* h_b2   = (const float*)d_in[28];
    float* out = (float*)d_out;

    float *p_vmix, *p_h1, *p_x2;
    cudaGetSymbolAddress((void**)&p_vmix, g_vmix);
    cudaGetSymbolAddress((void**)&p_h1,   g_h1);
    cudaGetSymbolAddress((void**)&p_x2,   g_x2);

    // Block 1: vmix GEMM (36864x128 @ 128x128), 32-row tiles -> 1152 CTAs
    sgemm32<128,false,false,false><<<NATOMS*3/32, 256>>>(vector_rep, mix_W1, nullptr, p_vmix);
    // h1 = silu([srep | ||vV||] @ sc1_W1 + b1)  (x1 built in the A-loader; 384 CTAs)
    sgemm32<192,true,true,true><<<NATOMS/32, 256>>>(scalar_rep, sc1_W1, sc1_b1, p_h1);
    // x2 = h1 @ sc1_W2 + b2   (split/silu handled in block2)
    sgemm32<128,true,false,false><<<NATOMS/32, 256>>>(p_h1, sc1_W2, sc1_b2, p_x2);
    // Block 2 -> l0, l1  (one atom per warp, full occupancy, f32x2 GEMV)
    block2_kernel<<<NATOMS/8, 256>>>(mix_W2, sc2_W1, sc2_b1, sc2_W2, sc2_b2);
    // Pairwise MLPs + output assembly (f32x2 packed)
    pair_kernel<<<dim3(NA/8, NB), 256>>>(positions,
        vv_W1, vv_b1, vv_W2, vv_b2,
        vr_W1, vr_b1, vr_W2, vr_b2,
        s_W1,  s_b1,  s_W2,  s_b2,
        h_W1,  h_b1,  h_W2,  h_b2,
        out);
}

// round 14
// speedup vs baseline: 1.0083x; 1.0083x over previous
#include <cuda_runtime.h>
#include <math.h>

#define NB 128
#define NA 96
#define NATOMS (NB*NA)      // 12288
#define NIN 128
#define H1 64

typedef unsigned long long ull;

// ---------------- scratch (static device memory, no allocations) ----------------
__device__ float g_vmix[NATOMS*3*NIN];        // 36864 x 128
__device__ float g_h1[NATOMS*NIN];            // 12288 x 128
__device__ float g_x2[NATOMS*NIN];            // 12288 x 128
__device__ float g_l0[NATOMS];
__device__ float g_l1[NATOMS*3];

__device__ __forceinline__ float silu_f(float x) {
    return __fdividef(x, 1.0f + __expf(-x));
}
// fast silu via HW tanh: x*sigmoid(x) = y + y*tanh(y), y = x/2
__device__ __forceinline__ float silu_t(float x) {
    float y = 0.5f*x, t;
    asm("tanh.approx.f32 %0, %1;" : "=f"(t) : "f"(y));
    return fmaf(y, t, y);
}
__device__ __forceinline__ ull packf2(float lo, float hi) {
    ull r; asm("mov.b64 %0, {%1, %2};" : "=l"(r) : "f"(lo), "f"(hi)); return r;
}
__device__ __forceinline__ ull dupf2(float v) {
    ull r; asm("mov.b64 %0, {%1, %1};" : "=l"(r) : "f"(v)); return r;
}
__device__ __forceinline__ void unpackf2(ull v, float& lo, float& hi) {
    asm("mov.b64 {%0, %1}, %2;" : "=f"(lo), "=f"(hi) : "l"(v));
}
__device__ __forceinline__ ull ffma2(ull a, ull b, ull c) {
    ull d; asm("fma.rn.f32x2 %0, %1, %2, %3;" : "=l"(d) : "l"(a), "l"(b), "l"(c)); return d;
}

// ---------------- 32x128 SGEMM, double-buffered, f32x2 mainloop -------------------
// C = A(MxK)@B(Kx128)(+bias)(+silu)
// X1 mode: A column k<128 comes from srep (stride 128); k>=128 is ||vmix[n,:, k-128]||
template<int K, bool BIAS, bool SILU, bool X1>
__global__ __launch_bounds__(256) void sgemm32(
    const float* __restrict__ A, const float* __restrict__ B,
    const float* __restrict__ bias, float* __restrict__ C)
{
    __shared__ __align__(16) float As[2][16][36];
    __shared__ __align__(16) float Bs[2][16][128];
    const int tid = threadIdx.x;
    const int bm  = blockIdx.x * 32;
    const int ty  = tid >> 5;    // 0..7  -> rows ty*4..+3
    const int tx  = tid & 31;    // 0..31 -> cols tx*4..+3

    // A-load indices: 2 elems/thread
    const int am0 = (tid)       >> 4, ak0 = (tid)       & 15;
    const int am1 = (tid + 256) >> 4, ak1 = (tid + 256) & 15;

    float ra[2];
    float rb[8];

    auto loadA = [&](int k0, float* r) {
#pragma unroll
        for (int i = 0; i < 2; i++) {
            int m  = (i == 0) ? am0 : am1;
            int kk = (i == 0) ? ak0 : ak1;
            int k  = k0 + kk;
            int n  = bm + m;
            float v;
            if (X1) {
                if (k < 128) {
                    v = A[n*128 + k];
                } else {
                    int o = k - 128;
                    float a = g_vmix[(n*3+0)*128 + o];
                    float b = g_vmix[(n*3+1)*128 + o];
                    float d = g_vmix[(n*3+2)*128 + o];
                    v = sqrtf(a*a + b*b + d*d);
                }
            } else {
                v = A[n*K + k];
            }
            r[i] = v;
        }
    };
    auto loadB = [&](int k0, float* r) {
#pragma unroll
        for (int i = 0; i < 8; i++) {
            int idx = tid + i*256;
            int kk = idx >> 7, n = idx & 127;
            r[i] = B[(k0 + kk)*128 + n];
        }
    };
    auto stsA = [&](int buf, const float* r) {
        As[buf][ak0][am0] = r[0];
        As[buf][ak1][am1] = r[1];
    };
    auto stsB = [&](int buf, const float* r) {
#pragma unroll
        for (int i = 0; i < 8; i++) {
            int idx = tid + i*256;
            int kk = idx >> 7, n = idx & 127;
            Bs[buf][kk][n] = r[i];
        }
    };

    // packed accumulators: accp[i][0] = cols (4tx, 4tx+1), accp[i][1] = cols (4tx+2, 4tx+3)
    ull accp[4][2];
#pragma unroll
    for (int i = 0; i < 4; i++) { accp[i][0] = 0ull; accp[i][1] = 0ull; }

    loadA(0, ra); loadB(0, rb);
    stsA(0, ra);  stsB(0, rb);
    __syncthreads();

    const int NCH = K / 16;
#pragma unroll 2
    for (int ch = 0; ch < NCH; ch++) {
        int cur = ch & 1;
        if (ch + 1 < NCH) { loadA((ch+1)*16, ra); loadB((ch+1)*16, rb); }
#pragma unroll
        for (int kk = 0; kk < 16; kk++) {
            float4 a = *reinterpret_cast<const float4*>(&As[cur][kk][ty*4]);
            const ull* bp = reinterpret_cast<const ull*>(&Bs[cur][kk][tx*4]);
            ull b01 = bp[0], b23 = bp[1];
            ull a0 = dupf2(a.x), a1 = dupf2(a.y), a2 = dupf2(a.z), a3 = dupf2(a.w);
            accp[0][0] = ffma2(a0, b01, accp[0][0]); accp[0][1] = ffma2(a0, b23, accp[0][1]);
            accp[1][0] = ffma2(a1, b01, accp[1][0]); accp[1][1] = ffma2(a1, b23, accp[1][1]);
            accp[2][0] = ffma2(a2, b01, accp[2][0]); accp[2][1] = ffma2(a2, b23, accp[2][1]);
            accp[3][0] = ffma2(a3, b01, accp[3][0]); accp[3][1] = ffma2(a3, b23, accp[3][1]);
        }
        if (ch + 1 < NCH) {
            stsA(1-cur, ra); stsB(1-cur, rb);
            __syncthreads();
        }
    }

#pragma unroll
    for (int i = 0; i < 4; i++) {
        int row = bm + ty*4 + i;
        float f[4];
        unpackf2(accp[i][0], f[0], f[1]);
        unpackf2(accp[i][1], f[2], f[3]);
        float4 v;
#pragma unroll
        for (int j = 0; j < 4; j++) {
            int col = tx*4 + j;
            float x = f[j];
            if (BIAS) x += bias[col];
            if (SILU) x = silu_f(x);
            f[j] = x;
        }
        v.x=f[0]; v.y=f[1]; v.z=f[2]; v.w=f[3];
        *reinterpret_cast<float4*>(&C[row*128 + tx*4]) = v;
    }
}

// ---------------- gated block 2: one atom per warp, f32x2 GEMV ---------------------
// Lane owns output columns (2*lane, 2*lane+1): W1 rows via LDS.64 as packed f32x2.
__global__ __launch_bounds__(256) void block2_kernel(
    const float* __restrict__ mixW2, const float* __restrict__ W1,
    const float* __restrict__ b1,    const float* __restrict__ W2,
    const float* __restrict__ b2)
{
    __shared__ __align__(16) float sW1[65*64];
    __shared__ __align__(16) float sb1v[64], sW2v[128], sMix[128], sb2v[2];
    __shared__ float sx_buf[8][64];
    const int tid = threadIdx.x;
    for (int t = tid; t < 65*64/4; t += 256)
        reinterpret_cast<float4*>(sW1)[t] = reinterpret_cast<const float4*>(W1)[t];
    if (tid < 64)  sb1v[tid] = b1[tid];
    if (tid < 128) { sW2v[tid] = W2[tid]; sMix[tid] = mixW2[tid]; }
    if (tid < 2)   sb2v[tid] = b2[tid];
    __syncthreads();

    const int warp = tid >> 5, lane = tid & 31;
    const int n = blockIdx.x*8 + warp;

    const float m0a = sMix[lane*2],        m1a = sMix[lane*2+1];
    const float m0b = sMix[(lane+32)*2],   m1b = sMix[(lane+32)*2+1];

    float x2a = g_x2[n*128 + lane],      x2b = g_x2[n*128 + 32 + lane];
    float ga  = g_x2[n*128 + 64 + lane], gb  = g_x2[n*128 + 96 + lane];
    float pm[6];
#pragma unroll
    for (int d = 0; d < 3; d++) {
        float vWa = g_vmix[(n*3+d)*128 + 64 + lane];
        float vWb = g_vmix[(n*3+d)*128 + 96 + lane];
        float v1a = ga*vWa, v1b = gb*vWb;
        pm[d*2]   = v1a*m0a + v1b*m0b;
        pm[d*2+1] = v1a*m1a + v1b*m1b;
    }
#pragma unroll
    for (int off = 16; off > 0; off >>= 1)
#pragma unroll
        for (int q = 0; q < 6; q++)
            pm[q] += __shfl_xor_sync(0xffffffffu, pm[q], off);

    float vn = sqrtf(pm[0]*pm[0] + pm[2]*pm[2] + pm[4]*pm[4]);
    sx_buf[warp][lane] = silu_f(x2a); sx_buf[warp][lane+32] = silu_f(x2b);
    __syncwarp();

    const ull* W1d = reinterpret_cast<const ull*>(sW1);
    float2 b1p = reinterpret_cast<const float2*>(sb1v)[lane];
    float2 wvn = reinterpret_cast<const float2*>(sW1)[64*32 + lane];
    ull h2 = packf2(fmaf(vn, wvn.x, b1p.x), fmaf(vn, wvn.y, b1p.y));
#pragma unroll 16
    for (int k = 0; k < 64; k++) {
        ull svp = dupf2(sx_buf[warp][k]);
        h2 = ffma2(svp, W1d[k*32 + lane], h2);
    }
    float h2x, h2y; unpackf2(h2, h2x, h2y);
    h2x = silu_f(h2x); h2y = silu_f(h2y);
    float4 w2 = reinterpret_cast<const float4*>(sW2v)[lane];   // W2[2lane][0..1], W2[2lane+1][0..1]
    float y0 = h2x*w2.x + h2y*w2.z;
    float y1 = h2x*w2.y + h2y*w2.w;
#pragma unroll
    for (int off = 16; off > 0; off >>= 1) {
        y0 += __shfl_xor_sync(0xffffffffu, y0, off);
        y1 += __shfl_xor_sync(0xffffffffu, y1, off);
    }
    if (lane == 0) {
        g_l0[n] = y0 + sb2v[0];
        float g2 = y1 + sb2v[1];
        g_l1[n*3+0] = g2*pm[1];
        g_l1[n*3+1] = g2*pm[3];
        g_l1[n*3+2] = g2*pm[5];
    }
}

// ---------------- pairwise kernel: warp per i, 3 j's per lane, f32x2 packed --------
__global__ __launch_bounds__(256) void pair_kernel(
    const float* __restrict__ positions,
    const float* __restrict__ vvW1, const float* __restrict__ vvb1,
    const float* __restrict__ vvW2, const float* __restrict__ vvb2,
    const float* __restrict__ vrW1, const float* __restrict__ vrb1,
    const float* __restrict__ vrW2, const float* __restrict__ vrb2,
    const float* __restrict__ sW1,  const float* __restrict__ sb1,
    const float* __restrict__ sW2,  const float* __restrict__ sb2,
    const float* __restrict__ hW1,  const float* __restrict__ hb1,
    const float* __restrict__ hW2,  const float* __restrict__ hb2,
    float* __restrict__ out)
{
    __shared__ float s_vvW1[270], s_vrW1[270];
    __shared__ float s_vvb1[30], s_vrb1[30], s_sb1[30], s_hb1[30];
    __shared__ float s_sW1a[30], s_sW1b[30];
    __shared__ ull   s_vvW2p[30][4]; __shared__ float s_vvW2s[30];
    __shared__ ull   s_vrW2p[30][4]; __shared__ float s_vrW2s[30];
    __shared__ ull   s_sW2p[30][4];  __shared__ float s_sW2s[30];
    __shared__ ull   s_hW2p[30][4];  __shared__ float s_hW2s[30];
    __shared__ ull   s_hW1p[30][4];  __shared__ float s_hW1s[30];
    __shared__ float s_acc0[9], s_hb2[9];
    __shared__ float s_l1[NA*3], s_pos[NA*3], s_l0[NA];
    __shared__ float4 s_Ai4[8][30], s_Ari4[8][30];
    __shared__ float  s_Ci[8][30];

    const int tid  = threadIdx.x;
    const int b    = blockIdx.y;
    const int warp = tid >> 5, lane = tid & 31;
    const int i    = blockIdx.x*8 + warp;

    for (int t = tid; t < 270; t += 256) { s_vvW1[t] = vvW1[t]; s_vrW1[t] = vrW1[t]; }
    for (int t = tid; t < 120; t += 256) {
        int c = t >> 2, q = t & 3;
        s_vvW2p[c][q] = packf2(vvW2[c*9+2*q], vvW2[c*9+2*q+1]);
        s_vrW2p[c][q] = packf2(vrW2[c*9+2*q], vrW2[c*9+2*q+1]);
        s_sW2p[c][q]  = packf2(sW2 [c*9+2*q], sW2 [c*9+2*q+1]);
        s_hW2p[c][q]  = packf2(hW2 [c*9+2*q], hW2 [c*9+2*q+1]);
        s_hW1p[c][q]  = packf2(hW1[(2*q)*30+c], hW1[(2*q+1)*30+c]);
    }
    if (tid < 30) {
        s_vvW2s[tid] = vvW2[tid*9+8]; s_vrW2s[tid] = vrW2[tid*9+8];
        s_sW2s[tid]  = sW2[tid*9+8];  s_hW2s[tid]  = hW2[tid*9+8];
        s_hW1s[tid]  = hW1[8*30+tid];
        s_vvb1[tid]  = vvb1[tid]; s_vrb1[tid] = vrb1[tid];
        s_sb1[tid]   = sb1[tid];  s_hb1[tid]  = hb1[tid];
        s_sW1a[tid]  = sW1[tid];  s_sW1b[tid] = sW1[30+tid];
    }
    if (tid < 9) { s_hb2[tid] = hb2[tid]; s_acc0[tid] = vvb2[tid]+vrb2[tid]+sb2[tid]; }

    const int nbase = b*NA;
    for (int t = tid; t < NA*3; t += 256) { s_l1[t] = g_l1[nbase*3 + t]; s_pos[t] = positions[nbase*3 + t]; }
    for (int t = tid; t < NA;   t += 256) s_l0[t] = g_l0[nbase + t];
    __syncthreads();

    // per-warp precompute for fixed i: A[c][l] = sum_k l1i[k]*W1[(3k+l)*30+c], [3]=bias
    const float l1i0 = s_l1[i*3], l1i1 = s_l1[i*3+1], l1i2 = s_l1[i*3+2];
    const float l0i  = s_l0[i];
    for (int c = lane; c < 30; c += 32) {
        float a[3], ar[3];
#pragma unroll
        for (int l = 0; l < 3; l++) {
            a[l]  = l1i0*s_vvW1[l*30+c] + l1i1*s_vvW1[(3+l)*30+c] + l1i2*s_vvW1[(6+l)*30+c];
            ar[l] = l1i0*s_vrW1[l*30+c] + l1i1*s_vrW1[(3+l)*30+c] + l1i2*s_vrW1[(6+l)*30+c];
        }
        s_Ai4[warp][c]  = make_float4(a[0],  a[1],  a[2],  s_vvb1[c]);
        s_Ari4[warp][c] = make_float4(ar[0], ar[1], ar[2], s_vrb1[c]);
        s_Ci[warp][c]   = s_sb1[c] + l0i*s_sW1a[c];
    }
    __syncwarp();

    float vj[3][3], pj[3][3], l0j[3];
#pragma unroll
    for (int r = 0; r < 3; r++) {
        int j = lane + r*32;
#pragma unroll
        for (int l = 0; l < 3; l++) { vj[r][l] = s_l1[j*3+l]; pj[r][l] = s_pos[j*3+l]; }
        l0j[r] = s_l0[j];
    }

    ull   accp[3][4];
    float acc8[3];
#pragma unroll
    for (int r = 0; r < 3; r++) {
#pragma unroll
        for (int q = 0; q < 4; q++) accp[r][q] = packf2(s_acc0[2*q], s_acc0[2*q+1]);
        acc8[r] = s_acc0[8];
    }

    // vv MLP
#pragma unroll 2
    for (int c = 0; c < 30; c++) {
        float4 A = s_Ai4[warp][c];
        ull w0 = s_vvW2p[c][0], w1 = s_vvW2p[c][1], w2 = s_vvW2p[c][2], w3 = s_vvW2p[c][3];
        float w8 = s_vvW2s[c];
#pragma unroll
        for (int r = 0; r < 3; r++) {
            float x = fmaf(A.x, vj[r][0], fmaf(A.y, vj[r][1], fmaf(A.z, vj[r][2], A.w)));
            float h = silu_t(x);
            ull hp = packf2(h, h);
            accp[r][0] = ffma2(hp, w0, accp[r][0]);
            accp[r][1] = ffma2(hp, w1, accp[r][1]);
            accp[r][2] = ffma2(hp, w2, accp[r][2]);
            accp[r][3] = ffma2(hp, w3, accp[r][3]);
            acc8[r] = fmaf(h, w8, acc8[r]);
        }
    }
    // vr MLP
#pragma unroll 2
    for (int c = 0; c < 30; c++) {
        float4 A = s_Ari4[warp][c];
        ull w0 = s_vrW2p[c][0], w1 = s_vrW2p[c][1], w2 = s_vrW2p[c][2], w3 = s_vrW2p[c][3];
        float w8 = s_vrW2s[c];
#pragma unroll
        for (int r = 0; r < 3; r++) {
            float x = fmaf(A.x, pj[r][0], fmaf(A.y, pj[r][1], fmaf(A.z, pj[r][2], A.w)));
            float h = silu_t(x);
            ull hp = packf2(h, h);
            accp[r][0] = ffma2(hp, w0, accp[r][0]);
            accp[r][1] = ffma2(hp, w1, accp[r][1]);
            accp[r][2] = ffma2(hp, w2, accp[r][2]);
            accp[r][3] = ffma2(hp, w3, accp[r][3]);
            acc8[r] = fmaf(h, w8, acc8[r]);
        }
    }
    // sp MLP
#pragma unroll 2
    for (int c = 0; c < 30; c++) {
        float ci = s_Ci[warp][c], wb = s_sW1b[c];
        ull w0 = s_sW2p[c][0], w1 = s_sW2p[c][1], w2 = s_sW2p[c][2], w3 = s_sW2p[c][3];
        float w8 = s_sW2s[c];
#pragma unroll
        for (int r = 0; r < 3; r++) {
            float h = silu_t(fmaf(l0j[r], wb, ci));
            ull hp = packf2(h, h);
            accp[r][0] = ffma2(hp, w0, accp[r][0]);
            accp[r][1] = ffma2(hp, w1, accp[r][1]);
            accp[r][2] = ffma2(hp, w2, accp[r][2]);
            accp[r][3] = ffma2(hp, w3, accp[r][3]);
            acc8[r] = fmaf(h, w8, acc8[r]);
        }
    }
    // final h MLP
    ull   o9p[3][4];
    float o9s[3];
#pragma unroll
    for (int r = 0; r < 3; r++) {
#pragma unroll
        for (int q = 0; q < 4; q++) o9p[r][q] = packf2(s_hb2[2*q], s_hb2[2*q+1]);
        o9s[r] = s_hb2[8];
    }
#pragma unroll 2
    for (int c = 0; c < 30; c++) {
        ull a0 = s_hW1p[c][0], a1 = s_hW1p[c][1], a2 = s_hW1p[c][2], a3 = s_hW1p[c][3];
        float a8 = s_hW1s[c], bb = s_hb1[c];
        ull b0 = s_hW2p[c][0], b1 = s_hW2p[c][1], b2 = s_hW2p[c][2], b3 = s_hW2p[c][3];
        float b8 = s_hW2s[c];
#pragma unroll
        for (int r = 0; r < 3; r++) {
            ull hs = packf2(bb, 0.f);
            hs = ffma2(accp[r][0], a0, hs);
            hs = ffma2(accp[r][1], a1, hs);
            hs = ffma2(accp[r][2], a2, hs);
            hs = ffma2(accp[r][3], a3, hs);
            float lo, hi; unpackf2(hs, lo, hi);
            float x = fmaf(acc8[r], a8, lo + hi);
            float h = silu_t(x);
            ull hp = packf2(h, h);
            o9p[r][0] = ffma2(hp, b0, o9p[r][0]);
            o9p[r][1] = ffma2(hp, b1, o9p[r][1]);
            o9p[r][2] = ffma2(hp, b2, o9p[r][2]);
            o9p[r][3] = ffma2(hp, b3, o9p[r][3]);
            o9s[r] = fmaf(h, b8, o9s[r]);
        }
    }
    // write: out[((b*A+i)*3+k)*(3A) + j*3 + l], t = 3k+l
    const int rowbase = (b*NA + i)*3;
#pragma unroll
    for (int r = 0; r < 3; r++) {
        float f[9];
#pragma unroll
        for (int q = 0; q < 4; q++) unpackf2(o9p[r][q], f[2*q], f[2*q+1]);
        f[8] = o9s[r];
        int j = lane + r*32;
#pragma unroll
        for (int k = 0; k < 3; k++)
#pragma unroll
            for (int l = 0; l < 3; l++)
                out[(rowbase + k)*(3*NA) + j*3 + l] = f[3*k + l];
    }
}

// ---------------- launcher ----------------------------------------------------------
extern "C" void kernel_launch(void* const* d_in, const int* in_sizes, int n_in,
                              void* d_out, int out_size)
{
    (void)in_sizes; (void)n_in; (void)out_size;
    const float* positions  = (const float*)d_in[0];
    const float* scalar_rep = (const float*)d_in[1];
    const float* vector_rep = (const float*)d_in[2];
    const float* mix_W1 = (const float*)d_in[3];
    const float* sc1_W1 = (const float*)d_in[4];
    const float* sc1_b1 = (const float*)d_in[5];
    const float* sc1_W2 = (const float*)d_in[6];
    const float* sc1_b2 = (const float*)d_in[7];
    const float* mix_W2 = (const float*)d_in[8];
    const float* sc2_W1 = (const float*)d_in[9];
    const float* sc2_b1 = (const float*)d_in[10];
    const float* sc2_W2 = (const float*)d_in[11];
    const float* sc2_b2 = (const float*)d_in[12];
    const float* vv_W1  = (const float*)d_in[13];
    const float* vv_b1  = (const float*)d_in[14];
    const float* vv_W2  = (const float*)d_in[15];
    const float* vv_b2  = (const float*)d_in[16];
    const float* vr_W1  = (const float*)d_in[17];
    const float* vr_b1  = (const float*)d_in[18];
    const float* vr_W2  = (const float*)d_in[19];
    const float* vr_b2  = (const float*)d_in[20];
    const float* s_W1   = (const float*)d_in[21];
    const float* s_b1   = (const float*)d_in[22];
    const float* s_W2   = (const float*)d_in[23];
    const float* s_b2   = (const float*)d_in[24];
    const float* h_W1   = (const float*)d_in[25];
    const float* h_b1   = (const float*)d_in[26];
    const float* h_W2   = (const float*)d_in[27];
    const float* h_b2   = (const float*)d_in[28];
    float* out = (float*)d_out;

    float *p_vmix, *p_h1, *p_x2;
    cudaGetSymbolAddress((void**)&p_vmix, g_vmix);
    cudaGetSymbolAddress((void**)&p_h1,   g_h1);
    cudaGetSymbolAddress((void**)&p_x2,   g_x2);

    // Block 1: vmix GEMM (36864x128 @ 128x128), 32-row tiles -> 1152 CTAs
    sgemm32<128,false,false,false><<<NATOMS*3/32, 256>>>(vector_rep, mix_W1, nullptr, p_vmix);
    // h1 = silu([srep | ||vV||] @ sc1_W1 + b1)  (x1 built in the A-loader; 384 CTAs)
    sgemm32<192,true,true,true><<<NATOMS/32, 256>>>(scalar_rep, sc1_W1, sc1_b1, p_h1);
    // x2 = h1 @ sc1_W2 + b2   (split/silu handled in block2)
    sgemm32<128,true,false,false><<<NATOMS/32, 256>>>(p_h1, sc1_W2, sc1_b2, p_x2);
    // Block 2 -> l0, l1  (one atom per warp, full occupancy, f32x2 GEMV)
    block2_kernel<<<NATOMS/8, 256>>>(mix_W2, sc2_W1, sc2_b1, sc2_W2, sc2_b2);
    // Pairwise MLPs + output assembly (f32x2 packed)
    pair_kernel<<<dim3(NA/8, NB), 256>>>(positions,
        vv_W1, vv_b1, vv_W2, vv_b2,
        vr_W1, vr_b1, vr_W2, vr_b2,
        s_W1,  s_b1,  s_W2,  s_b2,
        h_W1,  h_b1,  h_W2,  h_b2,
        out);
}